// round 2
// baseline (speedup 1.0000x reference)
#include <cuda_runtime.h>
#include <math.h>

// Problem constants
#define BB 2
#define HH 12
#define SS 2048
#define DD 64
#define CH 128     // key chunk cached in smem
#define QT 8       // queries per block (1 per warp)
#define NT 256     // threads per block

#define KPAD 76    // K smem row stride (floats): conflict-free LDS.128
#define VPAD 66    // V smem row stride (floats): conflict-free LDS.64

#define SMEM_FLOATS (CH*KPAD + CH*VPAD + QT*DD + QT*CH)
#define SMEM_BYTES  (SMEM_FLOATS * 4)

__device__ int g_cnt[BB];
__device__ int g_idx[BB][SS];

// ---------------------------------------------------------------------------
// Stable index list of global positions per batch (generic w.r.t. mask).
// 1024 threads, 2 positions each, block-wide exclusive scan.
// ---------------------------------------------------------------------------
__global__ void build_idx_kernel(const int* __restrict__ mask)
{
    int b = blockIdx.x;
    const int* m = mask + b * SS;
    int t = threadIdx.x;            // 0..1023
    int lane = t & 31, w = t >> 5;  // 32 warps
    __shared__ int wsum[32];

    int p0 = 2 * t, p1 = 2 * t + 1;
    int f0 = (m[p0] > 0);
    int f1 = (m[p1] > 0);
    int s = f0 + f1;

    int x = s;  // inclusive warp scan
    #pragma unroll
    for (int o = 1; o < 32; o <<= 1) {
        int y = __shfl_up_sync(0xffffffffu, x, o);
        if (lane >= o) x += y;
    }
    if (lane == 31) wsum[w] = x;
    __syncthreads();
    if (w == 0) {
        int y = wsum[lane];
        #pragma unroll
        for (int o = 1; o < 32; o <<= 1) {
            int z = __shfl_up_sync(0xffffffffu, y, o);
            if (lane >= o) y += z;
        }
        wsum[lane] = y;
    }
    __syncthreads();

    int excl = x - s + (w ? wsum[w - 1] : 0);
    if (f0) g_idx[b][excl] = p0;
    if (f1) g_idx[b][excl + f0] = p1;
    if (t == 1023) g_cnt[b] = excl + s;
}

__device__ __forceinline__ float warp_max_f(float x)
{
    #pragma unroll
    for (int o = 16; o; o >>= 1) x = fmaxf(x, __shfl_xor_sync(0xffffffffu, x, o));
    return x;
}
__device__ __forceinline__ float warp_sum_f(float x)
{
    #pragma unroll
    for (int o = 16; o; o >>= 1) x += __shfl_xor_sync(0xffffffffu, x, o);
    return x;
}

// ---------------------------------------------------------------------------
// Kernel 2: global-key attention for ALL queries.
// Writes the full probs row (computed head + zero tail) and context.
// One warp per query, 8 queries share smem K/V chunks.
// ---------------------------------------------------------------------------
__global__ void __launch_bounds__(NT)
gkey_attn_kernel(const float* __restrict__ Q, const float* __restrict__ K,
                 const float* __restrict__ V, float* __restrict__ ctx,
                 float* __restrict__ probs)
{
    extern __shared__ float sm[];
    float* sK = sm;                 // CH * KPAD
    float* sV = sK + CH * KPAD;     // CH * VPAD
    float* sQ = sV + CH * VPAD;     // QT * DD
    float* sP = sQ + QT * DD;       // QT * CH

    int b = blockIdx.z, h = blockIdx.y;
    int qbase = blockIdx.x * QT;
    int cnt = g_cnt[b];
    const int* idx = g_idx[b];
    int t = threadIdx.x, lane = t & 31, w = t >> 5;
    size_t bh = (size_t)b * HH + h;
    const float* Qb = Q + bh * SS * DD;
    const float* Kb = K + bh * SS * DD;
    const float* Vb = V + bh * SS * DD;

    for (int i = t; i < QT * DD; i += NT)
        sQ[i] = Qb[(size_t)(qbase + (i >> 6)) * DD + (i & 63)];

    int qp = qbase + w;
    float m = -INFINITY, l = 0.f;

    // ---- Pass A: running max + sum over gathered global keys ----
    for (int base = 0; base < cnt; base += CH) {
        int rem = min(CH, cnt - base);
        __syncthreads();
        for (int i = t; i < CH * DD; i += NT) {
            int key = i >> 6, d = i & 63;
            float kv = 0.f, vv = 0.f;
            if (key < rem) {
                size_t r = (size_t)idx[base + key] * DD + d;
                kv = Kb[r]; vv = Vb[r];
            }
            sK[key * KPAD + d] = kv;
            sV[key * VPAD + d] = vv;
        }
        __syncthreads();

        float sj[4] = {0.f, 0.f, 0.f, 0.f};
        #pragma unroll
        for (int d = 0; d < DD; d += 4) {
            float4 qd = *(const float4*)&sQ[w * DD + d];
            #pragma unroll
            for (int j = 0; j < 4; j++) {
                float4 kk = *(const float4*)&sK[(lane + 32 * j) * KPAD + d];
                sj[j] += qd.x * kk.x + qd.y * kk.y + qd.z * kk.z + qd.w * kk.w;
            }
        }
        float cm = -INFINITY;
        #pragma unroll
        for (int j = 0; j < 4; j++) {
            sj[j] = (lane + 32 * j < rem) ? sj[j] * 0.125f : -INFINITY;
            cm = fmaxf(cm, sj[j]);
        }
        cm = warp_max_f(cm);
        float nm = fmaxf(m, cm);
        float ps = 0.f;
        #pragma unroll
        for (int j = 0; j < 4; j++) ps += __expf(sj[j] - nm);
        l = l * __expf(m - nm) + warp_sum_f(ps);
        m = nm;
    }

    float inv_l = __frcp_rn(l);
    bool reload = (cnt > CH);       // single-chunk case keeps smem tiles live
    float a0 = 0.f, a1 = 0.f;
    size_t row = bh * SS + qp;
    float* prow = probs + row * SS;
    float* sPw = &sP[w * CH];

    // ---- Pass B: probs + context ----
    for (int base = 0; base < cnt; base += CH) {
        int rem = min(CH, cnt - base);
        if (reload) {
            __syncthreads();
            for (int i = t; i < CH * DD; i += NT) {
                int key = i >> 6, d = i & 63;
                float kv = 0.f, vv = 0.f;
                if (key < rem) {
                    size_t r = (size_t)idx[base + key] * DD + d;
                    kv = Kb[r]; vv = Vb[r];
                }
                sK[key * KPAD + d] = kv;
                sV[key * VPAD + d] = vv;
            }
            __syncthreads();
        }
        float sj[4] = {0.f, 0.f, 0.f, 0.f};
        #pragma unroll
        for (int d = 0; d < DD; d += 4) {
            float4 qd = *(const float4*)&sQ[w * DD + d];
            #pragma unroll
            for (int j = 0; j < 4; j++) {
                float4 kk = *(const float4*)&sK[(lane + 32 * j) * KPAD + d];
                sj[j] += qd.x * kk.x + qd.y * kk.y + qd.z * kk.z + qd.w * kk.w;
            }
        }
        #pragma unroll
        for (int j = 0; j < 4; j++) {
            int key = lane + 32 * j;
            float p = (key < rem) ? __expf(sj[j] * 0.125f - m) * inv_l : 0.f;
            sPw[key] = p;
        }
        __syncwarp();
        // vectorized probs store through sP
        int nv = rem >> 2;
        const float4* sp4 = (const float4*)sPw;
        float4* pr4 = (float4*)&prow[base];
        for (int i = lane; i < nv; i += 32) pr4[i] = sp4[i];
        for (int i = (nv << 2) + lane; i < rem; i += 32) prow[base + i] = sPw[i];
        // PV accumulate: lane owns dims 2*lane, 2*lane+1
        #pragma unroll 8
        for (int key = 0; key < CH; key++) {
            float pp = sPw[key];
            float2 vv = *(const float2*)&sV[key * VPAD + 2 * lane];
            a0 += pp * vv.x;
            a1 += pp * vv.y;
        }
    }

    // ---- zero tail of probs row: columns [cnt, SS) ----
    int a4 = (cnt + 3) & ~3;
    for (int x2 = cnt + lane; x2 < a4 && x2 < SS; x2 += 32) prow[x2] = 0.f;
    float4 z4 = make_float4(0.f, 0.f, 0.f, 0.f);
    float4* prowf4 = (float4*)prow;
    for (int x2 = (a4 >> 2) + lane; x2 < (SS >> 2); x2 += 32) prowf4[x2] = z4;

    // ---- context (overwritten later for global queries) ----
    *(float2*)&ctx[row * DD + 2 * lane] = make_float2(a0, a1);
}

// ---------------------------------------------------------------------------
// Kernel 3: full attention for global queries only (flash-style online softmax).
// ---------------------------------------------------------------------------
__global__ void __launch_bounds__(NT)
full_attn_kernel(const float* __restrict__ Q, const float* __restrict__ K,
                 const float* __restrict__ V, float* __restrict__ ctx)
{
    int b = blockIdx.z, h = blockIdx.y;
    int cnt = g_cnt[b];
    int s0 = blockIdx.x * QT;
    if (s0 >= cnt) return;          // uniform exit

    extern __shared__ float sm[];
    float* sK = sm;
    float* sV = sK + CH * KPAD;
    float* sQ = sV + CH * VPAD;
    float* sP = sQ + QT * DD;

    const int* idx = g_idx[b];
    int t = threadIdx.x, lane = t & 31, w = t >> 5;
    size_t bh = (size_t)b * HH + h;
    const float* Qb = Q + bh * SS * DD;
    const float* Kb = K + bh * SS * DD;
    const float* Vb = V + bh * SS * DD;

    for (int i = t; i < QT * DD; i += NT) {
        int r = i >> 6;
        int slot = s0 + r;
        sQ[i] = (slot < cnt) ? Qb[(size_t)idx[slot] * DD + (i & 63)] : 0.f;
    }

    int slot = s0 + w;
    bool act = (slot < cnt);
    int qp = act ? idx[slot] : 0;
    float m = -INFINITY, l = 0.f, a0 = 0.f, a1 = 0.f;
    float* sPw = &sP[w * CH];

    for (int base = 0; base < SS; base += CH) {
        __syncthreads();
        for (int i = t; i < CH * DD; i += NT) {
            int key = i >> 6, d = i & 63;
            size_t r = (size_t)(base + key) * DD + d;
            sK[key * KPAD + d] = Kb[r];
            sV[key * VPAD + d] = Vb[r];
        }
        __syncthreads();

        float sj[4] = {0.f, 0.f, 0.f, 0.f};
        #pragma unroll
        for (int d = 0; d < DD; d += 4) {
            float4 qd = *(const float4*)&sQ[w * DD + d];
            #pragma unroll
            for (int j = 0; j < 4; j++) {
                float4 kk = *(const float4*)&sK[(lane + 32 * j) * KPAD + d];
                sj[j] += qd.x * kk.x + qd.y * kk.y + qd.z * kk.z + qd.w * kk.w;
            }
        }
        float cm = -INFINITY;
        #pragma unroll
        for (int j = 0; j < 4; j++) {
            sj[j] *= 0.125f;
            cm = fmaxf(cm, sj[j]);
        }
        cm = warp_max_f(cm);
        float nm = fmaxf(m, cm);
        float corr = __expf(m - nm);
        float ps = 0.f;
        #pragma unroll
        for (int j = 0; j < 4; j++) {
            float p = __expf(sj[j] - nm);
            ps += p;
            sPw[lane + 32 * j] = p;
        }
        l = l * corr + warp_sum_f(ps);
        a0 *= corr; a1 *= corr;
        m = nm;
        __syncwarp();
        #pragma unroll 8
        for (int key = 0; key < CH; key++) {
            float pp = sPw[key];
            float2 vv = *(const float2*)&sV[key * VPAD + 2 * lane];
            a0 += pp * vv.x;
            a1 += pp * vv.y;
        }
    }

    if (act) {
        float invl = __frcp_rn(l);
        *(float2*)&ctx[(bh * SS + (size_t)qp) * DD + 2 * lane] =
            make_float2(a0 * invl, a1 * invl);
    }
}

// ---------------------------------------------------------------------------
extern "C" void kernel_launch(void* const* d_in, const int* in_sizes, int n_in,
                              void* d_out, int out_size)
{
    const float* q = (const float*)d_in[0];
    const float* k = (const float*)d_in[1];
    const float* v = (const float*)d_in[2];
    const int* mask = (const int*)d_in[3];
    float* out = (float*)d_out;
    float* ctx = out;
    float* probs = out + (size_t)BB * HH * SS * DD;

    cudaFuncSetAttribute(gkey_attn_kernel,
                         cudaFuncAttributeMaxDynamicSharedMemorySize, SMEM_BYTES);
    cudaFuncSetAttribute(full_attn_kernel,
                         cudaFuncAttributeMaxDynamicSharedMemorySize, SMEM_BYTES);

    build_idx_kernel<<<BB, 1024>>>(mask);
    dim3 grid(SS / QT, HH, BB);
    gkey_attn_kernel<<<grid, NT, SMEM_BYTES>>>(q, k, v, ctx, probs);
    full_attn_kernel<<<grid, NT, SMEM_BYTES>>>(q, k, v, ctx);
}

// round 4
// speedup vs baseline: 3.0343x; 3.0343x over previous
#include <cuda_runtime.h>
#include <math.h>

// Problem constants
#define BB 2
#define HH 12
#define SS 2048
#define DD 64
#define CH 128            // key chunk cached in smem
#define QW 4              // queries per warp
#define WARPS 8
#define NT 256
#define QT (QW*WARPS)     // 32 queries per block
#define NGQ (SS/QT)       // 64 gkey query tiles
#define SPLITS 4
#define SPLIT_KEYS (SS/SPLITS)   // 512
#define NFT (SS/QT)       // worst-case full-attn query tiles
#define GRIDX (NGQ + NFT*SPLITS) // 320

#define KPAD 76           // K smem row stride: conflict-free LDS.128 (stride 12 banks)
#define VPAD 68           // V smem row stride: aligned STS.128, conflict-free LDS.64

#define SMEM_FLOATS (CH*KPAD + CH*VPAD + QT*DD + QT*CH)
#define SMEM_BYTES  (SMEM_FLOATS * 4)

__device__ int g_cnt[BB];
__device__ int g_idx[BB][SS];
// split-KV partials for the full-attention (global-query) path
__device__ float2 g_pml[BB*HH*SS*SPLITS];
__device__ float  g_pacc[(size_t)BB*HH*SS*SPLITS*DD];

// packed f32x2 FMA (FFMA2) — halves FMA instruction count
__device__ __forceinline__ void fma2(float2& a, float2 x, float2 y)
{
    asm("fma.rn.f32x2 %0, %1, %2, %0;"
        : "+l"(*reinterpret_cast<unsigned long long*>(&a))
        : "l"(*reinterpret_cast<const unsigned long long*>(&x)),
          "l"(*reinterpret_cast<const unsigned long long*>(&y)));
}

__device__ __forceinline__ float warp_max_f(float x)
{
    #pragma unroll
    for (int o = 16; o; o >>= 1) x = fmaxf(x, __shfl_xor_sync(0xffffffffu, x, o));
    return x;
}
__device__ __forceinline__ float warp_sum_f(float x)
{
    #pragma unroll
    for (int o = 16; o; o >>= 1) x += __shfl_xor_sync(0xffffffffu, x, o);
    return x;
}

// ---------------------------------------------------------------------------
// Stable index list of global positions per batch.
// ---------------------------------------------------------------------------
__global__ void build_idx_kernel(const int* __restrict__ mask)
{
    int b = blockIdx.x;
    const int* m = mask + b * SS;
    int t = threadIdx.x;
    int lane = t & 31, w = t >> 5;
    __shared__ int wsum[32];

    int p0 = 2 * t, p1 = 2 * t + 1;
    int f0 = (m[p0] > 0);
    int f1 = (m[p1] > 0);
    int s = f0 + f1;

    int x = s;
    #pragma unroll
    for (int o = 1; o < 32; o <<= 1) {
        int y = __shfl_up_sync(0xffffffffu, x, o);
        if (lane >= o) x += y;
    }
    if (lane == 31) wsum[w] = x;
    __syncthreads();
    if (w == 0) {
        int y = wsum[lane];
        #pragma unroll
        for (int o = 1; o < 32; o <<= 1) {
            int z = __shfl_up_sync(0xffffffffu, y, o);
            if (lane >= o) y += z;
        }
        wsum[lane] = y;
    }
    __syncthreads();

    int excl = x - s + (w ? wsum[w - 1] : 0);
    if (f0) g_idx[b][excl] = p0;
    if (f1) g_idx[b][excl + f0] = p1;
    if (t == 1023) g_cnt[b] = excl + s;
}

// ---------------------------------------------------------------------------
// Shared building blocks
// ---------------------------------------------------------------------------
// QK: warp computes 4 queries x 128 keys; lane owns keys lane, lane+32, +64, +96.
__device__ __forceinline__ void qk_dot(const float* __restrict__ sK,
                                       const float* __restrict__ sQ,
                                       int w, int lane, float sj[QW][4])
{
    float2 s2[QW][4];
    #pragma unroll
    for (int q = 0; q < QW; q++)
        #pragma unroll
        for (int j = 0; j < 4; j++) s2[q][j] = make_float2(0.f, 0.f);

    #pragma unroll
    for (int d = 0; d < DD; d += 4) {
        float4 kk[4];
        #pragma unroll
        for (int j = 0; j < 4; j++)
            kk[j] = *(const float4*)&sK[(lane + 32 * j) * KPAD + d];
        #pragma unroll
        for (int q = 0; q < QW; q++) {
            float4 qd = *(const float4*)&sQ[(w * QW + q) * DD + d];
            #pragma unroll
            for (int j = 0; j < 4; j++) {
                fma2(s2[q][j], make_float2(qd.x, qd.y), make_float2(kk[j].x, kk[j].y));
                fma2(s2[q][j], make_float2(qd.z, qd.w), make_float2(kk[j].z, kk[j].w));
            }
        }
    }
    #pragma unroll
    for (int q = 0; q < QW; q++)
        #pragma unroll
        for (int j = 0; j < 4; j++)
            sj[q][j] = (s2[q][j].x + s2[q][j].y) * 0.125f;
}

// PV: accumulate acc[q] (dims 2*lane, 2*lane+1) over all CH keys from sP/sV.
__device__ __forceinline__ void pv_acc(const float* __restrict__ sV,
                                       const float* __restrict__ sP,
                                       int w, int lane, float2 acc[QW])
{
    #pragma unroll 4
    for (int k4 = 0; k4 < CH / 4; k4++) {
        float p4[QW][4];
        #pragma unroll
        for (int q = 0; q < QW; q++) {
            float4 v = *(const float4*)&sP[(w * QW + q) * CH + 4 * k4];
            p4[q][0] = v.x; p4[q][1] = v.y; p4[q][2] = v.z; p4[q][3] = v.w;
        }
        #pragma unroll
        for (int j = 0; j < 4; j++) {
            float2 v2 = *(const float2*)&sV[(4 * k4 + j) * VPAD + 2 * lane];
            #pragma unroll
            for (int q = 0; q < QW; q++)
                fma2(acc[q], make_float2(p4[q][j], p4[q][j]), v2);
        }
    }
}

// Gathered K/V fill (gkey path): float4 loads/stores.
__device__ __forceinline__ void fill_gather(float* __restrict__ sK, float* __restrict__ sV,
                                            const float* __restrict__ Kb,
                                            const float* __restrict__ Vb,
                                            const int* __restrict__ idxp, int rem, int t)
{
    for (int i = t; i < CH * DD / 4; i += NT) {
        int key = i >> 4, dq = (i & 15) << 2;
        float4 kv = make_float4(0.f, 0.f, 0.f, 0.f), vv = kv;
        if (key < rem) {
            size_t r = (size_t)__ldg(&idxp[key]) * DD + dq;
            kv = *(const float4*)&Kb[r];
            vv = *(const float4*)&Vb[r];
        }
        *(float4*)&sK[key * KPAD + dq] = kv;
        *(float4*)&sV[key * VPAD + dq] = vv;
    }
}

// Contiguous K/V fill (full-attn path).
__device__ __forceinline__ void fill_lin(float* __restrict__ sK, float* __restrict__ sV,
                                         const float* __restrict__ Kb,
                                         const float* __restrict__ Vb,
                                         int base, int t)
{
    for (int i = t; i < CH * DD / 4; i += NT) {
        int key = i >> 4, dq = (i & 15) << 2;
        size_t r = (size_t)(base + key) * DD + dq;
        *(float4*)&sK[key * KPAD + dq] = *(const float4*)&Kb[r];
        *(float4*)&sV[key * VPAD + dq] = *(const float4*)&Vb[r];
    }
}

// ---------------------------------------------------------------------------
// Mega kernel: blocks x < NGQ do gkey attention (all queries, probs + ctx);
// blocks x >= NGQ do split-KV full attention for global queries (partials).
// ---------------------------------------------------------------------------
__global__ void __launch_bounds__(NT, 2)
mega_kernel(const float* __restrict__ Q, const float* __restrict__ K,
            const float* __restrict__ V, const int* __restrict__ mask,
            float* __restrict__ ctx, float* __restrict__ probs)
{
    extern __shared__ float sm[];
    float* sK = sm;                  // CH * KPAD
    float* sV = sK + CH * KPAD;      // CH * VPAD
    float* sQ = sV + CH * VPAD;      // QT * DD
    float* sP = sQ + QT * DD;        // QT * CH

    int b = blockIdx.z, h = blockIdx.y, x = blockIdx.x;
    int cnt = g_cnt[b];
    const int* idx = g_idx[b];
    int t = threadIdx.x, lane = t & 31, w = t >> 5;
    size_t bh = (size_t)b * HH + h;
    const float* Qb = Q + bh * SS * DD;
    const float* Kb = K + bh * SS * DD;
    const float* Vb = V + bh * SS * DD;

    if (x < NGQ) {
        // ================= gkey path =================
        int qbase = x * QT;
        for (int i = t; i < QT * DD / 4; i += NT) {
            int qr = i >> 4, dq = (i & 15) << 2;
            *(float4*)&sQ[qr * DD + dq] = *(const float4*)&Qb[(size_t)(qbase + qr) * DD + dq];
        }

        bool single = (cnt <= CH);
        float m[QW], l[QW], sjs[QW][4];
        #pragma unroll
        for (int q = 0; q < QW; q++) { m[q] = -INFINITY; l[q] = 0.f; }

        // ---- Pass A: running max/sum ----
        for (int base = 0; base < cnt; base += CH) {
            int rem = min(CH, cnt - base);
            __syncthreads();
            fill_gather(sK, sV, Kb, Vb, idx + base, rem, t);
            __syncthreads();

            float sj[QW][4];
            qk_dot(sK, sQ, w, lane, sj);
            #pragma unroll
            for (int q = 0; q < QW; q++) {
                float cm = -INFINITY;
                #pragma unroll
                for (int j = 0; j < 4; j++) {
                    if (lane + 32 * j >= rem) sj[q][j] = -INFINITY;
                    cm = fmaxf(cm, sj[q][j]);
                }
                cm = warp_max_f(cm);
                float nm = fmaxf(m[q], cm);
                float ps = 0.f;
                #pragma unroll
                for (int j = 0; j < 4; j++) ps += __expf(sj[q][j] - nm);
                l[q] = l[q] * __expf(m[q] - nm) + warp_sum_f(ps);
                m[q] = nm;
                if (single)
                    #pragma unroll
                    for (int j = 0; j < 4; j++) sjs[q][j] = sj[q][j];
            }
        }

        float invl[QW];
        #pragma unroll
        for (int q = 0; q < QW; q++) invl[q] = __frcp_rn(l[q]);

        float2 acc[QW];
        #pragma unroll
        for (int q = 0; q < QW; q++) acc[q] = make_float2(0.f, 0.f);

        // ---- Pass B: probs + context ----
        for (int base = 0; base < cnt; base += CH) {
            float sj[QW][4];
            if (single) {
                #pragma unroll
                for (int q = 0; q < QW; q++)
                    #pragma unroll
                    for (int j = 0; j < 4; j++) sj[q][j] = sjs[q][j];
            } else {
                int rem = min(CH, cnt - base);
                __syncthreads();
                fill_gather(sK, sV, Kb, Vb, idx + base, rem, t);
                __syncthreads();
                qk_dot(sK, sQ, w, lane, sj);
                #pragma unroll
                for (int q = 0; q < QW; q++)
                    #pragma unroll
                    for (int j = 0; j < 4; j++)
                        if (lane + 32 * j >= rem) sj[q][j] = -INFINITY;
            }
            #pragma unroll
            for (int q = 0; q < QW; q++)
                #pragma unroll
                for (int j = 0; j < 4; j++)
                    sP[(w * QW + q) * CH + lane + 32 * j] = __expf(sj[q][j] - m[q]) * invl[q];
            __syncwarp();
            // probs head store (coalesced float4 via sP transpose)
            #pragma unroll
            for (int q = 0; q < QW; q++) {
                int qp = qbase + w * QW + q;
                float4 pv4 = *(const float4*)&sP[(w * QW + q) * CH + 4 * lane];
                *(float4*)&probs[(bh * SS + qp) * SS + base + 4 * lane] = pv4;
            }
            pv_acc(sV, sP, w, lane, acc);
        }

        // ---- zero tail + ctx ----
        int a4 = (cnt + 3) & ~3;
        float4 z4 = make_float4(0.f, 0.f, 0.f, 0.f);
        #pragma unroll
        for (int q = 0; q < QW; q++) {
            int qp = qbase + w * QW + q;
            float* prow = probs + (bh * SS + qp) * SS;
            for (int i = cnt + lane; i < a4 && i < SS; i += 32) prow[i] = 0.f;
            float4* pr4 = (float4*)prow;
            for (int i = (a4 >> 2) + lane; i < (SS >> 2); i += 32) pr4[i] = z4;
            // ctx only for non-global queries (global ones come from reduce kernel)
            if (mask[b * SS + qp] <= 0)
                *(float2*)&ctx[(bh * SS + qp) * DD + 2 * lane] = acc[q];
        }
    } else {
        // ================= full-attention split path =================
        int r = x - NGQ;
        int tile = r / SPLITS, split = r % SPLITS;
        if (tile * QT >= cnt) return;

        for (int i = t; i < QT * DD; i += NT) {
            int slot = tile * QT + (i >> 6);
            sQ[i] = (slot < cnt) ? Qb[(size_t)idx[slot] * DD + (i & 63)] : 0.f;
        }

        float m[QW], l[QW];
        float2 acc[QW];
        #pragma unroll
        for (int q = 0; q < QW; q++) { m[q] = -INFINITY; l[q] = 0.f; acc[q] = make_float2(0.f, 0.f); }

        int kbase0 = split * SPLIT_KEYS;
        for (int c = 0; c < SPLIT_KEYS; c += CH) {
            __syncthreads();
            fill_lin(sK, sV, Kb, Vb, kbase0 + c, t);
            __syncthreads();

            float sj[QW][4];
            qk_dot(sK, sQ, w, lane, sj);
            #pragma unroll
            for (int q = 0; q < QW; q++) {
                float cm = fmaxf(fmaxf(sj[q][0], sj[q][1]), fmaxf(sj[q][2], sj[q][3]));
                cm = warp_max_f(cm);
                float nm = fmaxf(m[q], cm);
                float corr = __expf(m[q] - nm);
                float ps = 0.f;
                #pragma unroll
                for (int j = 0; j < 4; j++) {
                    float p = __expf(sj[q][j] - nm);
                    ps += p;
                    sP[(w * QW + q) * CH + lane + 32 * j] = p;
                }
                l[q] = l[q] * corr + warp_sum_f(ps);
                acc[q].x *= corr; acc[q].y *= corr;
                m[q] = nm;
            }
            __syncwarp();
            pv_acc(sV, sP, w, lane, acc);
        }

        #pragma unroll
        for (int q = 0; q < QW; q++) {
            int slot = tile * QT + w * QW + q;
            if (slot < cnt) {
                size_t ip = (bh * SS + slot) * SPLITS + split;
                if (lane == 0) g_pml[ip] = make_float2(m[q], l[q]);
                *(float2*)&g_pacc[ip * DD + 2 * lane] = acc[q];
            }
        }
    }
}

// ---------------------------------------------------------------------------
// Split reduce: combine SPLITS partials -> ctx for global queries.
// One warp per global query slot.
// ---------------------------------------------------------------------------
__global__ void __launch_bounds__(256)
reduce_kernel(float* __restrict__ ctx)
{
    int b = blockIdx.z, h = blockIdx.y;
    int cnt = g_cnt[b];
    int slot = blockIdx.x * 8 + (threadIdx.x >> 5);
    if (slot >= cnt) return;
    int lane = threadIdx.x & 31;
    size_t bh = (size_t)b * HH + h;
    size_t base = (bh * SS + slot) * SPLITS;

    float2 mls[SPLITS];
    float M = -INFINITY;
    #pragma unroll
    for (int s = 0; s < SPLITS; s++) {
        mls[s] = g_pml[base + s];
        M = fmaxf(M, mls[s].x);
    }
    float L = 0.f;
    float ax = 0.f, ay = 0.f;
    #pragma unroll
    for (int s = 0; s < SPLITS; s++) {
        float e = __expf(mls[s].x - M);
        L += e * mls[s].y;
        float2 pa = *(const float2*)&g_pacc[(base + s) * DD + 2 * lane];
        ax += e * pa.x;
        ay += e * pa.y;
    }
    float invL = __frcp_rn(L);
    int qp = g_idx[b][slot];
    *(float2*)&ctx[(bh * SS + qp) * DD + 2 * lane] = make_float2(ax * invL, ay * invL);
}

// ---------------------------------------------------------------------------
extern "C" void kernel_launch(void* const* d_in, const int* in_sizes, int n_in,
                              void* d_out, int out_size)
{
    const float* q = (const float*)d_in[0];
    const float* k = (const float*)d_in[1];
    const float* v = (const float*)d_in[2];
    const int* mask = (const int*)d_in[3];
    float* out = (float*)d_out;
    float* ctx = out;
    float* probs = out + (size_t)BB * HH * SS * DD;

    cudaFuncSetAttribute(mega_kernel,
                         cudaFuncAttributeMaxDynamicSharedMemorySize, SMEM_BYTES);

    build_idx_kernel<<<BB, 1024>>>(mask);
    mega_kernel<<<dim3(GRIDX, HH, BB), NT, SMEM_BYTES>>>(q, k, v, mask, ctx, probs);
    reduce_kernel<<<dim3(SS / 8, HH, BB), 256>>>(ctx);
}